// round 5
// baseline (speedup 1.0000x reference)
#include <cuda_runtime.h>

// Problem constants
#define BATCH 4
#define SEQ   4096
#define DM    1024
#define NH    16
#define EP    256
#define HDIM  64
#define CHUNK 512   // query rows per attention CTA

// ---------------------------------------------------------------------------
// Scratch (static __device__ arrays — allocation APIs are forbidden)
// ---------------------------------------------------------------------------
__device__ float g_q[(size_t)BATCH * SEQ * DM];   // 67 MB
__device__ float g_k[(size_t)BATCH * SEQ * DM];   // 67 MB
__device__ float g_v[(size_t)BATCH * SEQ * DM];   // 67 MB
__device__ float g_kp[(size_t)BATCH * EP * DM];   // 4 MB  (k_proj, [b][e][d])
__device__ float g_vp[(size_t)BATCH * EP * DM];   // 4 MB  (v_proj)

// ---------------------------------------------------------------------------
// SGEMM (NN): C[M,Nn] = A[M,K] @ B[K,Nn], all row-major.
// 128x128 block, BK=16, 256 threads, 8x8 per-thread microtile.
// All dims are multiples of the tile sizes for this problem -> no edge checks.
// ---------------------------------------------------------------------------
__global__ __launch_bounds__(256) void sgemm_nn(
    const float* __restrict__ A, const float* __restrict__ B,
    float* __restrict__ C, int M, int Nn, int K)
{
    __shared__ float As[16][132];   // padded: reduces transpose-store conflicts
    __shared__ float Bs[16][128];

    const int tid  = threadIdx.x;
    const int row0 = blockIdx.y * 128;
    const int col0 = blockIdx.x * 128;
    const int tx = (tid & 15) * 8;
    const int ty = (tid >> 4) * 8;

    float acc[8][8];
#pragma unroll
    for (int i = 0; i < 8; i++)
#pragma unroll
        for (int j = 0; j < 8; j++) acc[i][j] = 0.f;

    for (int k0 = 0; k0 < K; k0 += 16) {
#pragma unroll
        for (int t = 0; t < 2; t++) {
            int i  = tid + t * 256;
            // A tile: 128 rows x 16 cols -> store transposed As[k][m]
            int ar = i >> 2, ac = (i & 3) << 2;
            float4 av = *(const float4*)(A + (size_t)(row0 + ar) * K + k0 + ac);
            As[ac + 0][ar] = av.x;
            As[ac + 1][ar] = av.y;
            As[ac + 2][ar] = av.z;
            As[ac + 3][ar] = av.w;
            // B tile: 16 rows x 128 cols -> direct
            int br = i >> 5, bc = (i & 31) << 2;
            *(float4*)&Bs[br][bc] = *(const float4*)(B + (size_t)(k0 + br) * Nn + col0 + bc);
        }
        __syncthreads();
#pragma unroll
        for (int kk = 0; kk < 16; kk++) {
            float a[8], b[8];
            *(float4*)&a[0] = *(float4*)&As[kk][ty];
            *(float4*)&a[4] = *(float4*)&As[kk][ty + 4];
            *(float4*)&b[0] = *(float4*)&Bs[kk][tx];
            *(float4*)&b[4] = *(float4*)&Bs[kk][tx + 4];
#pragma unroll
            for (int i = 0; i < 8; i++)
#pragma unroll
                for (int j = 0; j < 8; j++)
                    acc[i][j] += a[i] * b[j];
        }
        __syncthreads();
    }
#pragma unroll
    for (int i = 0; i < 8; i++) {
        float* cp = C + (size_t)(row0 + ty + i) * Nn + col0 + tx;
        *(float4*)cp       = make_float4(acc[i][0], acc[i][1], acc[i][2], acc[i][3]);
        *(float4*)(cp + 4) = make_float4(acc[i][4], acc[i][5], acc[i][6], acc[i][7]);
    }
}

// ---------------------------------------------------------------------------
// Batched SGEMM (TN): C_z[M,Nn] = A^T[M,K] @ B_z[K,Nn]   (A is [K,M] row-major,
// shared across z; B and C are z-strided). Used for k_proj/v_proj:
//   kp[b][e][d] = sum_n P[n][e] * k[b][n][d]
// ---------------------------------------------------------------------------
__global__ __launch_bounds__(256) void sgemm_tn_b(
    const float* __restrict__ A, const float* __restrict__ Bb,
    float* __restrict__ Cb, int M, int Nn, int K,
    size_t strideB, size_t strideC)
{
    __shared__ float As[16][132];
    __shared__ float Bs[16][128];

    const float* B = Bb + blockIdx.z * strideB;
    float*       C = Cb + blockIdx.z * strideC;

    const int tid  = threadIdx.x;
    const int row0 = blockIdx.y * 128;   // M (= e) block
    const int col0 = blockIdx.x * 128;   // Nn (= d) block
    const int tx = (tid & 15) * 8;
    const int ty = (tid >> 4) * 8;

    float acc[8][8];
#pragma unroll
    for (int i = 0; i < 8; i++)
#pragma unroll
        for (int j = 0; j < 8; j++) acc[i][j] = 0.f;

    for (int k0 = 0; k0 < K; k0 += 16) {
#pragma unroll
        for (int t = 0; t < 2; t++) {
            int i  = tid + t * 256;
            // A tile: A[k0+r][row0+c], 16 rows x 128 cols -> As[k][m] direct
            int ar = i >> 5, ac = (i & 31) << 2;
            *(float4*)&As[ar][ac] = *(const float4*)(A + (size_t)(k0 + ar) * M + row0 + ac);
            // B tile
            int br = ar, bc = ac;
            *(float4*)&Bs[br][bc] = *(const float4*)(B + (size_t)(k0 + br) * Nn + col0 + bc);
        }
        __syncthreads();
#pragma unroll
        for (int kk = 0; kk < 16; kk++) {
            float a[8], b[8];
            *(float4*)&a[0] = *(float4*)&As[kk][ty];
            *(float4*)&a[4] = *(float4*)&As[kk][ty + 4];
            *(float4*)&b[0] = *(float4*)&Bs[kk][tx];
            *(float4*)&b[4] = *(float4*)&Bs[kk][tx + 4];
#pragma unroll
            for (int i = 0; i < 8; i++)
#pragma unroll
                for (int j = 0; j < 8; j++)
                    acc[i][j] += a[i] * b[j];
        }
        __syncthreads();
    }
#pragma unroll
    for (int i = 0; i < 8; i++) {
        float* cp = C + (size_t)(row0 + ty + i) * Nn + col0 + tx;
        *(float4*)cp       = make_float4(acc[i][0], acc[i][1], acc[i][2], acc[i][3]);
        *(float4*)(cp + 4) = make_float4(acc[i][4], acc[i][5], acc[i][6], acc[i][7]);
    }
}

// ---------------------------------------------------------------------------
// Fused attention: per (b,h) load k_proj/v_proj tiles (256x64 fp32 each) into
// SMEM once, then each thread owns a query row and does an online-softmax
// sweep over E=256 keys. Never materializes the [B,H,N,E] score tensor.
// Grid: (SEQ/CHUNK, BATCH*NH), 256 threads, 131072 B dynamic smem.
// ---------------------------------------------------------------------------
__global__ __launch_bounds__(256) void attn_fused(
    const float* __restrict__ q, const float* __restrict__ kp,
    const float* __restrict__ vp, float* __restrict__ out)
{
    extern __shared__ float smem[];
    float* Ks = smem;               // [EP][HDIM]
    float* Vs = smem + EP * HDIM;   // [EP][HDIM]

    const int bh = blockIdx.y;
    const int b  = bh >> 4;
    const int h  = bh & 15;
    const int n0 = blockIdx.x * CHUNK;

    const float* kpb = kp + (size_t)b * EP * DM + h * HDIM;
    const float* vpb = vp + (size_t)b * EP * DM + h * HDIM;

    for (int i = threadIdx.x; i < EP * HDIM / 4; i += 256) {
        int e = i >> 4, d4 = (i & 15) << 2;
        ((float4*)Ks)[i] = *(const float4*)(kpb + (size_t)e * DM + d4);
        ((float4*)Vs)[i] = *(const float4*)(vpb + (size_t)e * DM + d4);
    }
    __syncthreads();

    for (int r = threadIdx.x; r < CHUNK; r += 256) {
        const int n = n0 + r;
        const float4* qrow = (const float4*)(q + (size_t)(b * SEQ + n) * DM + h * HDIM);

        float4 qr[16];
#pragma unroll
        for (int i = 0; i < 16; i++) qr[i] = qrow[i];

        float4 acc[16];
#pragma unroll
        for (int i = 0; i < 16; i++) acc[i] = make_float4(0.f, 0.f, 0.f, 0.f);

        float m = -1e30f, l = 0.f;

        for (int e = 0; e < EP; e++) {
            const float4* kr = (const float4*)(Ks + e * HDIM);
            float s0 = 0.f, s1 = 0.f, s2 = 0.f, s3 = 0.f;  // 4 chains for ILP
#pragma unroll
            for (int i = 0; i < 16; i++) {
                float4 kv = kr[i];
                s0 += qr[i].x * kv.x;
                s1 += qr[i].y * kv.y;
                s2 += qr[i].z * kv.z;
                s3 += qr[i].w * kv.w;
            }
            float s = ((s0 + s1) + (s2 + s3)) * 0.125f;  // 1/sqrt(64)

            if (s > m) {                 // rare after the first few e
                float c = __expf(m - s); // 0 on the first hit (m = -1e30)
                l *= c;
#pragma unroll
                for (int i = 0; i < 16; i++) {
                    acc[i].x *= c; acc[i].y *= c;
                    acc[i].z *= c; acc[i].w *= c;
                }
                m = s;
            }
            float p = __expf(s - m);
            l += p;

            const float4* vr = (const float4*)(Vs + e * HDIM);
#pragma unroll
            for (int i = 0; i < 16; i++) {
                float4 vv = vr[i];
                acc[i].x += p * vv.x; acc[i].y += p * vv.y;
                acc[i].z += p * vv.z; acc[i].w += p * vv.w;
            }
        }

        float inv = 1.f / l;
        float4* orow = (float4*)(out + (size_t)(b * SEQ + n) * DM + h * HDIM);
#pragma unroll
        for (int i = 0; i < 16; i++)
            orow[i] = make_float4(acc[i].x * inv, acc[i].y * inv,
                                  acc[i].z * inv, acc[i].w * inv);
    }
}

// ---------------------------------------------------------------------------
// Launch: 6 kernels, all graph-capturable, no allocations.
// Input order (metadata): x, proj_weight_all, W_q, W_k, W_v. Output fp32.
// ---------------------------------------------------------------------------
extern "C" void kernel_launch(void* const* d_in, const int* in_sizes, int n_in,
                              void* d_out, int out_size)
{
    const float* x  = (const float*)d_in[0];
    const float* P  = (const float*)d_in[1];
    const float* Wq = (const float*)d_in[2];
    const float* Wk = (const float*)d_in[3];
    const float* Wv = (const float*)d_in[4];
    float* out = (float*)d_out;

    void *pq, *pk, *pv, *pkp, *pvp;
    cudaGetSymbolAddress(&pq,  g_q);
    cudaGetSymbolAddress(&pk,  g_k);
    cudaGetSymbolAddress(&pv,  g_v);
    cudaGetSymbolAddress(&pkp, g_kp);
    cudaGetSymbolAddress(&pvp, g_vp);

    // QKV projections: [16384,1024] @ [1024,1024]
    dim3 gqkv(DM / 128, (BATCH * SEQ) / 128);
    sgemm_nn<<<gqkv, 256>>>(x, Wq, (float*)pq, BATCH * SEQ, DM, DM);
    sgemm_nn<<<gqkv, 256>>>(x, Wk, (float*)pk, BATCH * SEQ, DM, DM);
    sgemm_nn<<<gqkv, 256>>>(x, Wv, (float*)pv, BATCH * SEQ, DM, DM);

    // Low-rank sequence projection per batch: kp[b] = P^T @ k[b]  ([256,1024])
    dim3 gproj(DM / 128, EP / 128, BATCH);
    sgemm_tn_b<<<gproj, 256>>>(P, (const float*)pk, (float*)pkp,
                               EP, DM, SEQ, (size_t)SEQ * DM, (size_t)EP * DM);
    sgemm_tn_b<<<gproj, 256>>>(P, (const float*)pv, (float*)pvp,
                               EP, DM, SEQ, (size_t)SEQ * DM, (size_t)EP * DM);

    // Fused attention (scores + softmax + AV + head concat)
    int smem_bytes = 2 * EP * HDIM * (int)sizeof(float);  // 131072
    cudaFuncSetAttribute(attn_fused, cudaFuncAttributeMaxDynamicSharedMemorySize,
                         smem_bytes);
    attn_fused<<<dim3(SEQ / CHUNK, BATCH * NH), 256, smem_bytes>>>(
        (const float*)pq, (const float*)pkp, (const float*)pvp, out);
}

// round 7
// speedup vs baseline: 2.1393x; 2.1393x over previous
#include <cuda_runtime.h>
#include <cuda_bf16.h>

// Problem constants
#define BATCH 4
#define SEQ   4096
#define DM    1024
#define NH    16
#define EP    256
#define HDIM  64
#define CHUNK 512
#define MROWS (BATCH*SEQ)     // 16384
#define KA    2048            // split-K columns: [hi | lo]
#define NC    3072            // q|k|v output columns

// ---------------------------------------------------------------------------
// Scratch (static __device__ arrays — allocation APIs are forbidden)
// ---------------------------------------------------------------------------
__device__ unsigned short g_A [(size_t)MROWS * KA];        // x hi|lo bf16
__device__ unsigned short g_Bt[(size_t)NC * KA];           // [Wq|Wk|Wv]^T hi|lo
__device__ float          g_q [(size_t)MROWS * DM];        // q fp32
__device__ unsigned short g_kth[(size_t)BATCH * DM * SEQ]; // k^T hi [b][d][n]
__device__ unsigned short g_ktl[(size_t)BATCH * DM * SEQ];
__device__ unsigned short g_vth[(size_t)BATCH * DM * SEQ];
__device__ unsigned short g_vtl[(size_t)BATCH * DM * SEQ];
__device__ unsigned short g_Pth[(size_t)EP * SEQ];         // P^T hi [e][n]
__device__ unsigned short g_Ptl[(size_t)EP * SEQ];
__device__ float          g_kp[(size_t)BATCH * EP * DM];   // k_proj [b][e][d]
__device__ float          g_vp[(size_t)BATCH * EP * DM];

// ---------------------------------------------------------------------------
// Baseline-PTX helpers (no 'a'-target features): cp.async, ldmatrix, mma.sync
// ---------------------------------------------------------------------------
__device__ __forceinline__ unsigned smem_to_u32(const void* p) {
    unsigned a;
    asm("{ .reg .u64 t; cvta.to.shared.u64 t, %1; cvt.u32.u64 %0, t; }"
        : "=r"(a) : "l"(p));
    return a;
}
__device__ __forceinline__ void cp_async16(unsigned saddr, const void* g) {
    asm volatile("cp.async.cg.shared.global [%0], [%1], 16;"
                 :: "r"(saddr), "l"(g) : "memory");
}
#define CP_COMMIT() asm volatile("cp.async.commit_group;" ::: "memory")
#define CP_WAIT1()  asm volatile("cp.async.wait_group 1;" ::: "memory")
#define CP_WAIT0()  asm volatile("cp.async.wait_group 0;" ::: "memory")

__device__ __forceinline__ void ldm_x4(unsigned& r0, unsigned& r1,
                                       unsigned& r2, unsigned& r3, unsigned a) {
    asm volatile("ldmatrix.sync.aligned.m8n8.x4.shared.b16 {%0,%1,%2,%3}, [%4];"
                 : "=r"(r0), "=r"(r1), "=r"(r2), "=r"(r3) : "r"(a));
}
__device__ __forceinline__ void mma16816(float* c, const unsigned* a,
                                         const unsigned* b) {
    asm volatile(
        "mma.sync.aligned.m16n8k16.row.col.f32.bf16.bf16.f32 "
        "{%0,%1,%2,%3}, {%4,%5,%6,%7}, {%8,%9}, {%0,%1,%2,%3};"
        : "+f"(c[0]), "+f"(c[1]), "+f"(c[2]), "+f"(c[3])
        : "r"(a[0]), "r"(a[1]), "r"(a[2]), "r"(a[3]), "r"(b[0]), "r"(b[1]));
}

// Swizzled 16B-chunk offset inside a [rows][32 bf16] tile (64 B/row):
// phase = (row&1)*4 + (c ^ ((row>>1)&3))  -> 8 distinct phases per 8 rows.
__device__ __forceinline__ unsigned tile_off(int row, int c) {
    return (unsigned)(row * 64 + ((c ^ ((row >> 1) & 3)) << 4));
}

// ---------------------------------------------------------------------------
// fp32 -> bf16 hi/lo split
// ---------------------------------------------------------------------------
__device__ __forceinline__ void split_bf16(float v, unsigned short& h, unsigned short& l) {
    __nv_bfloat16 hb = __float2bfloat16(v);
    __nv_bfloat16 lb = __float2bfloat16(v - __bfloat162float(hb));
    h = __bfloat16_as_ushort(hb);
    l = __bfloat16_as_ushort(lb);
}

__global__ __launch_bounds__(256) void conv_x(const float* __restrict__ x,
                                              unsigned short* __restrict__ A) {
    size_t i = ((size_t)blockIdx.x * 256 + threadIdx.x) * 4;
    float4 v = *(const float4*)(x + i);
    size_t row = i >> 10, c = i & 1023;
    unsigned short h[4], l[4];
    split_bf16(v.x, h[0], l[0]); split_bf16(v.y, h[1], l[1]);
    split_bf16(v.z, h[2], l[2]); split_bf16(v.w, h[3], l[3]);
    *(uint2*)(A + row * KA + c)        = *(uint2*)h;
    *(uint2*)(A + row * KA + 1024 + c) = *(uint2*)l;
}

__global__ __launch_bounds__(256) void conv_w(const float* __restrict__ Wq,
                                              const float* __restrict__ Wk,
                                              const float* __restrict__ Wv,
                                              unsigned short* __restrict__ Bt) {
    size_t i = (size_t)blockIdx.x * 256 + threadIdx.x;
    int z = (int)(i >> 20);
    int rem = (int)(i & 1048575);
    int k = rem >> 10, n = rem & 1023;
    const float* W = (z == 0) ? Wq : (z == 1) ? Wk : Wv;
    unsigned short h, l;
    split_bf16(W[(size_t)k * 1024 + n], h, l);
    size_t r = (size_t)(z * 1024 + n) * KA;
    Bt[r + k] = h;
    Bt[r + 1024 + k] = l;
}

__global__ __launch_bounds__(256) void conv_p(const float* __restrict__ P,
                                              unsigned short* __restrict__ Ph,
                                              unsigned short* __restrict__ Pl) {
    size_t i = (size_t)blockIdx.x * 256 + threadIdx.x;
    int n = (int)(i >> 8), e = (int)(i & 255);
    unsigned short h, l;
    split_bf16(P[i], h, l);
    Ph[(size_t)e * SEQ + n] = h;
    Pl[(size_t)e * SEQ + n] = l;
}

// ---------------------------------------------------------------------------
// Shared GEMM mainloop: C[128,128] = sum over 3 compensation passes of
//   Asel[r][koff+k] * Bsel[n][koff+k]  (both K-major rows),
// passes: (Ah,Bh), (Al,Bh), (Ah,Bl).  k-chunk 32, cp.async double buffer,
// 8 warps (2Mx4N), warp tile 64x32 via mma.m16n8k16.
// SMEM stages: stage s at s*16384 (A 8KB + B 8KB).
// ---------------------------------------------------------------------------
template<int KP32>
__device__ __forceinline__ void gemm_mainloop(
    const unsigned short* __restrict__ Ah, const unsigned short* __restrict__ Al,
    const unsigned short* __restrict__ Bh, const unsigned short* __restrict__ Bl,
    size_t lda, size_t ldb, unsigned sbase, float acc[4][4][4])
{
    const int tid = threadIdx.x;
    const int wid = tid >> 5, l = tid & 31;
    const int wm = wid & 1, wn = wid >> 1;
    constexpr int T = 3 * KP32;

    auto prefetch = [&](int t) {
        int buf = t & 1;
        int p   = t / KP32;
        int kt  = t % KP32;
        int koff = kt * 32;
        const unsigned short* sA = (p == 1) ? Al : Ah;
        const unsigned short* sB = (p == 2) ? Bl : Bh;
        unsigned abase = sbase + buf * 16384;
        unsigned bbase = abase + 8192;
#pragma unroll
        for (int j = 0; j < 2; j++) {
            int i = tid + j * 256;          // 512 chunks of 16B per tile
            int row = i >> 2, c = i & 3;
            unsigned so = tile_off(row, c);
            cp_async16(abase + so, sA + (size_t)row * lda + koff + c * 8);
            cp_async16(bbase + so, sB + (size_t)row * ldb + koff + c * 8);
        }
    };

    prefetch(0);
    CP_COMMIT();
    for (int t = 0; t < T; t++) {
        if (t + 1 < T) { prefetch(t + 1); CP_COMMIT(); CP_WAIT1(); }
        else           { CP_WAIT0(); }
        __syncthreads();
        unsigned abase = sbase + (t & 1) * 16384;
        unsigned bbase = abase + 8192;
#pragma unroll
        for (int s = 0; s < 2; s++) {
            unsigned af[4][4], bf[4][2];
#pragma unroll
            for (int tm = 0; tm < 4; tm++) {
                int row = wm * 64 + tm * 16 + (l & 15);
                int c   = 2 * s + (l >> 4);
                ldm_x4(af[tm][0], af[tm][1], af[tm][2], af[tm][3],
                       abase + tile_off(row, c));
            }
#pragma unroll
            for (int t2 = 0; t2 < 2; t2++) {
                int mi  = l >> 3;
                int row = wn * 32 + t2 * 16 + ((mi >> 1) << 3) + (l & 7);
                int c   = 2 * s + (mi & 1);
                ldm_x4(bf[2 * t2][0], bf[2 * t2][1], bf[2 * t2 + 1][0], bf[2 * t2 + 1][1],
                       bbase + tile_off(row, c));
            }
#pragma unroll
            for (int tm = 0; tm < 4; tm++)
#pragma unroll
                for (int tn = 0; tn < 4; tn++)
                    mma16816(acc[tm][tn], af[tm], bf[tn]);
        }
        __syncthreads();
    }
}

// Stage accumulators into SMEM fp32 [128][129] (pad -> conflict-free col reads)
__device__ __forceinline__ void stage_acc(float* Cs, float acc[4][4][4],
                                          int wid, int l) {
    const int wm = wid & 1, wn = wid >> 1;
#pragma unroll
    for (int tm = 0; tm < 4; tm++)
#pragma unroll
        for (int tn = 0; tn < 4; tn++) {
            int r  = wm * 64 + tm * 16 + (l >> 2);
            int cc = wn * 32 + tn * 8 + (l & 3) * 2;
            Cs[r * 129 + cc]           = acc[tm][tn][0];
            Cs[r * 129 + cc + 1]       = acc[tm][tn][1];
            Cs[(r + 8) * 129 + cc]     = acc[tm][tn][2];
            Cs[(r + 8) * 129 + cc + 1] = acc[tm][tn][3];
        }
}

#define GEMM_SMEM 66048   // 128*129*4 staging; mainloop uses first 32KB

// ---------------------------------------------------------------------------
// QKV GEMM: C[16384, 3072]. Tiles 128x128 -> grid (24, 128).
// Epilogue: cols 0-1023 -> q fp32; 1024-2047 -> kt hi/lo (transposed);
//           2048-3071 -> vt hi/lo (transposed).
// ---------------------------------------------------------------------------
__global__ __launch_bounds__(256) void gemm_qkv(
    const unsigned short* __restrict__ A, const unsigned short* __restrict__ Bt,
    float* __restrict__ outq,
    unsigned short* __restrict__ kth, unsigned short* __restrict__ ktl,
    unsigned short* __restrict__ vth, unsigned short* __restrict__ vtl)
{
    extern __shared__ char smem[];
    unsigned sbase = smem_to_u32(smem);
    const int tid = threadIdx.x, wid = tid >> 5, l = tid & 31;
    const int m0 = blockIdx.y * 128;
    const int c0 = blockIdx.x * 128;

    float acc[4][4][4];
#pragma unroll
    for (int i = 0; i < 4; i++)
#pragma unroll
        for (int j = 0; j < 4; j++)
#pragma unroll
            for (int k = 0; k < 4; k++) acc[i][j][k] = 0.f;

    const unsigned short* Abase = A + (size_t)m0 * KA;
    const unsigned short* Bbase = Bt + (size_t)c0 * KA;
    gemm_mainloop<32>(Abase, Abase + 1024, Bbase, Bbase + 1024, KA, KA, sbase, acc);

    float* Cs = (float*)smem;
    stage_acc(Cs, acc, wid, l);
    __syncthreads();

    const int mtx = c0 >> 10;       // 0=q, 1=k, 2=v
    const int cw  = c0 & 1023;
    if (mtx == 0) {
        for (int i = tid; i < 16384; i += 256) {
            int r = i >> 7, c = i & 127;
            outq[(size_t)(m0 + r) * DM + cw + c] = Cs[r * 129 + c];
        }
    } else {
        unsigned short* dh = (mtx == 1) ? kth : vth;
        unsigned short* dl = (mtx == 1) ? ktl : vtl;
        const int b = m0 >> 12, nb = m0 & 4095;
        for (int i = tid; i < 16384; i += 256) {
            int c = i >> 7, r = i & 127;    // lanes consecutive in r (=n): coalesced
            unsigned short h, lo;
            split_bf16(Cs[r * 129 + c], h, lo);
            size_t a = ((size_t)b * DM + cw + c) * SEQ + nb + r;
            dh[a] = h; dl[a] = lo;
        }
    }
}

// ---------------------------------------------------------------------------
// Projection GEMM: per (b,{k,v}): C[d=128-tile, e=128-tile] =
//   kt[b] (K-major over n, lda=SEQ) @ Pt (K-major, ldb=SEQ), K=4096 x 3 passes.
// grid (EP/128=2, DM/128=8, 2*BATCH=8). Output kp/vp [b][e][d] (transposed).
// ---------------------------------------------------------------------------
__global__ __launch_bounds__(256) void gemm_proj(
    const unsigned short* __restrict__ kth, const unsigned short* __restrict__ ktl,
    const unsigned short* __restrict__ vth, const unsigned short* __restrict__ vtl,
    const unsigned short* __restrict__ Pth, const unsigned short* __restrict__ Ptl,
    float* __restrict__ kp, float* __restrict__ vp)
{
    extern __shared__ char smem[];
    unsigned sbase = smem_to_u32(smem);
    const int tid = threadIdx.x, wid = tid >> 5, l = tid & 31;
    const int e0 = blockIdx.x * 128;
    const int d0 = blockIdx.y * 128;
    const int z  = blockIdx.z;
    const int b  = z >> 1;
    const int mtx = z & 1;          // 0=k, 1=v

    const unsigned short* Ah = (mtx ? vth : kth) + ((size_t)b * DM + d0) * SEQ;
    const unsigned short* Al = (mtx ? vtl : ktl) + ((size_t)b * DM + d0) * SEQ;
    const unsigned short* Bh = Pth + (size_t)e0 * SEQ;
    const unsigned short* Bl = Ptl + (size_t)e0 * SEQ;

    float acc[4][4][4];
#pragma unroll
    for (int i = 0; i < 4; i++)
#pragma unroll
        for (int j = 0; j < 4; j++)
#pragma unroll
            for (int k = 0; k < 4; k++) acc[i][j][k] = 0.f;

    gemm_mainloop<128>(Ah, Al, Bh, Bl, SEQ, SEQ, sbase, acc);

    float* Cs = (float*)smem;       // rows = d (M), cols = e (N)
    stage_acc(Cs, acc, wid, l);
    __syncthreads();

    float* out = (mtx ? vp : kp) + (size_t)b * EP * DM;
    for (int i = tid; i < 16384; i += 256) {
        int ce = i >> 7, r = i & 127;   // lanes consecutive in r (=d): coalesced
        out[(size_t)(e0 + ce) * DM + d0 + r] = Cs[r * 129 + ce];
    }
}

// ---------------------------------------------------------------------------
// Fused attention: per (b,h) K/V tiles resident in SMEM, online softmax.
// ---------------------------------------------------------------------------
__global__ __launch_bounds__(256) void attn_fused(
    const float* __restrict__ q, const float* __restrict__ kp,
    const float* __restrict__ vp, float* __restrict__ out)
{
    extern __shared__ float smemf[];
    float* Ks = smemf;
    float* Vs = smemf + EP * HDIM;

    const int bh = blockIdx.y;
    const int b  = bh >> 4;
    const int h  = bh & 15;
    const int n0 = blockIdx.x * CHUNK;

    const float* kpb = kp + (size_t)b * EP * DM + h * HDIM;
    const float* vpb = vp + (size_t)b * EP * DM + h * HDIM;

    for (int i = threadIdx.x; i < EP * HDIM / 4; i += 256) {
        int e = i >> 4, d4 = (i & 15) << 2;
        ((float4*)Ks)[i] = *(const float4*)(kpb + (size_t)e * DM + d4);
        ((float4*)Vs)[i] = *(const float4*)(vpb + (size_t)e * DM + d4);
    }
    __syncthreads();

    for (int r = threadIdx.x; r < CHUNK; r += 256) {
        const int n = n0 + r;
        const float4* qrow = (const float4*)(q + (size_t)(b * SEQ + n) * DM + h * HDIM);

        float4 qr[16];
#pragma unroll
        for (int i = 0; i < 16; i++) qr[i] = qrow[i];
        float4 acc[16];
#pragma unroll
        for (int i = 0; i < 16; i++) acc[i] = make_float4(0.f, 0.f, 0.f, 0.f);

        float m = -1e30f, l = 0.f;
        for (int e = 0; e < EP; e++) {
            const float4* kr = (const float4*)(Ks + e * HDIM);
            float s0 = 0.f, s1 = 0.f, s2 = 0.f, s3 = 0.f;
#pragma unroll
            for (int i = 0; i < 16; i++) {
                float4 kv = kr[i];
                s0 += qr[i].x * kv.x; s1 += qr[i].y * kv.y;
                s2 += qr[i].z * kv.z; s3 += qr[i].w * kv.w;
            }
            float s = ((s0 + s1) + (s2 + s3)) * 0.125f;
            if (s > m) {
                float c = __expf(m - s);
                l *= c;
#pragma unroll
                for (int i = 0; i < 16; i++) {
                    acc[i].x *= c; acc[i].y *= c; acc[i].z *= c; acc[i].w *= c;
                }
                m = s;
            }
            float p = __expf(s - m);
            l += p;
            const float4* vr = (const float4*)(Vs + e * HDIM);
#pragma unroll
            for (int i = 0; i < 16; i++) {
                float4 vv = vr[i];
                acc[i].x += p * vv.x; acc[i].y += p * vv.y;
                acc[i].z += p * vv.z; acc[i].w += p * vv.w;
            }
        }
        float inv = 1.f / l;
        float4* orow = (float4*)(out + (size_t)(b * SEQ + n) * DM + h * HDIM);
#pragma unroll
        for (int i = 0; i < 16; i++)
            orow[i] = make_float4(acc[i].x * inv, acc[i].y * inv,
                                  acc[i].z * inv, acc[i].w * inv);
    }
}

// ---------------------------------------------------------------------------
// Launch
// ---------------------------------------------------------------------------
extern "C" void kernel_launch(void* const* d_in, const int* in_sizes, int n_in,
                              void* d_out, int out_size)
{
    const float* x  = (const float*)d_in[0];
    const float* P  = (const float*)d_in[1];
    const float* Wq = (const float*)d_in[2];
    const float* Wk = (const float*)d_in[3];
    const float* Wv = (const float*)d_in[4];
    float* out = (float*)d_out;

    void *pA, *pBt, *pq, *pkth, *pktl, *pvth, *pvtl, *pPth, *pPtl, *pkp, *pvp;
    cudaGetSymbolAddress(&pA,   g_A);
    cudaGetSymbolAddress(&pBt,  g_Bt);
    cudaGetSymbolAddress(&pq,   g_q);
    cudaGetSymbolAddress(&pkth, g_kth);
    cudaGetSymbolAddress(&pktl, g_ktl);
    cudaGetSymbolAddress(&pvth, g_vth);
    cudaGetSymbolAddress(&pvtl, g_vtl);
    cudaGetSymbolAddress(&pPth, g_Pth);
    cudaGetSymbolAddress(&pPtl, g_Ptl);
    cudaGetSymbolAddress(&pkp,  g_kp);
    cudaGetSymbolAddress(&pvp,  g_vp);

    cudaFuncSetAttribute(gemm_qkv,  cudaFuncAttributeMaxDynamicSharedMemorySize, GEMM_SMEM);
    cudaFuncSetAttribute(gemm_proj, cudaFuncAttributeMaxDynamicSharedMemorySize, GEMM_SMEM);
    cudaFuncSetAttribute(attn_fused, cudaFuncAttributeMaxDynamicSharedMemorySize,
                         2 * EP * HDIM * (int)sizeof(float));

    // 1) hi/lo bf16 splits
    conv_x<<<(MROWS * DM) / (256 * 4), 256>>>(x, (unsigned short*)pA);
    conv_w<<<(3 * DM * DM) / 256, 256>>>(Wq, Wk, Wv, (unsigned short*)pBt);
    conv_p<<<(SEQ * EP) / 256, 256>>>(P, (unsigned short*)pPth, (unsigned short*)pPtl);

    // 2) QKV GEMM (mma.sync bf16, 3-pass compensated): grid 24 x 128
    gemm_qkv<<<dim3(NC / 128, MROWS / 128), 256, GEMM_SMEM>>>(
        (const unsigned short*)pA, (const unsigned short*)pBt,
        (float*)pq,
        (unsigned short*)pkth, (unsigned short*)pktl,
        (unsigned short*)pvth, (unsigned short*)pvtl);

    // 3) low-rank projection GEMMs: grid (2, 8, 8)
    gemm_proj<<<dim3(EP / 128, DM / 128, 2 * BATCH), 256, GEMM_SMEM>>>(
        (const unsigned short*)pkth, (const unsigned short*)pktl,
        (const unsigned short*)pvth, (const unsigned short*)pvtl,
        (const unsigned short*)pPth, (const unsigned short*)pPtl,
        (float*)pkp, (float*)pvp);

    // 4) fused attention
    attn_fused<<<dim3(SEQ / CHUNK, BATCH * NH), 256,
                 2 * EP * HDIM * (int)sizeof(float)>>>(
        (const float*)pq, (const float*)pkp, (const float*)pvp, out);
}